// round 1
// baseline (speedup 1.0000x reference)
#include <cuda_runtime.h>
#include <math.h>

#define DD 1024      // TTS_DIM
#define LL 3072      // LLAMA_DIM
#define NMEL 100
#define NB 4
#define NT_SEQ 1024
#define ROWS (NB*NT_SEQ)   // 4096

// ---------------- scratch (static device globals; no allocation) ----------------
__device__ float g_bufA[DD*DD];
__device__ float g_bufB[DD*DD];
__device__ float g_Q[DD*DD];
__device__ float g_Wc[LL*DD];
__device__ float g_bvec[DD];
__device__ float g_fused[ROWS*DD];
__device__ float g_h1[ROWS*DD];
__device__ float g_h2[ROWS*DD];

// ---------------- generic tiled SGEMM ----------------
// C[M,N] = op(A)[M,K] @ op(B)[K,N] (+ bias[n])
// TA: A stored [K,M] (use A[k*lda+m]); else A stored [M,K] (A[m*lda+k])
// TB: B stored [N,K] (use B[n*ldb+k]); else B stored [K,N] (B[k*ldb+n])
// EPI==0: C[m*ldc+n] = v
// EPI==1: mel transposed write: row m encodes (b,t); out[(b*NMEL+n)*NT_SEQ + t] = v
template<int BM,int BN,int BK,int TM,int TN,bool TA,bool TB,int EPI>
__global__ __launch_bounds__((BM/TM)*(BN/TN))
void gemm_kernel(const float* __restrict__ A, const float* __restrict__ B,
                 const float* __restrict__ bias, float* __restrict__ C,
                 int M, int N, int K, int lda, int ldb, int ldc)
{
    constexpr int NTH = (BM/TM)*(BN/TN);
    __shared__ float As[BK][BM];
    __shared__ float Bs[BK][BN];
    const int tid = threadIdx.x;
    const int tx  = tid % (BN/TN);
    const int ty  = tid / (BN/TN);
    const int m0  = blockIdx.y * BM;
    const int n0  = blockIdx.x * BN;

    float acc[TM][TN];
    #pragma unroll
    for (int i = 0; i < TM; ++i)
        #pragma unroll
        for (int j = 0; j < TN; ++j) acc[i][j] = 0.f;

    for (int k0 = 0; k0 < K; k0 += BK) {
        // ---- load A tile into As[k][m] ----
        if (!TA) {
            #pragma unroll
            for (int t = tid; t < BM*BK; t += NTH) {
                int m = t / BK, k = t % BK;
                int gm = m0 + m;
                As[k][m] = (gm < M) ? A[(long)gm*lda + (k0+k)] : 0.f;
            }
        } else {
            #pragma unroll
            for (int t = tid; t < BM*BK; t += NTH) {
                int m = t % BM, k = t / BM;
                int gm = m0 + m;
                As[k][m] = (gm < M) ? A[(long)(k0+k)*lda + gm] : 0.f;
            }
        }
        // ---- load B tile into Bs[k][n] ----
        if (!TB) {
            #pragma unroll
            for (int t = tid; t < BK*BN; t += NTH) {
                int n = t % BN, k = t / BN;
                int gn = n0 + n;
                Bs[k][n] = (gn < N) ? B[(long)(k0+k)*ldb + gn] : 0.f;
            }
        } else {
            #pragma unroll
            for (int t = tid; t < BK*BN; t += NTH) {
                int k = t % BK, n = t / BK;
                int gn = n0 + n;
                Bs[k][n] = (gn < N) ? B[(long)gn*ldb + (k0+k)] : 0.f;
            }
        }
        __syncthreads();

        #pragma unroll
        for (int k = 0; k < BK; ++k) {
            float a[TM], b[TN];
            #pragma unroll
            for (int i = 0; i < TM; ++i) a[i] = As[k][ty*TM + i];
            #pragma unroll
            for (int j = 0; j < TN; ++j) b[j] = Bs[k][tx*TN + j];
            #pragma unroll
            for (int i = 0; i < TM; ++i)
                #pragma unroll
                for (int j = 0; j < TN; ++j)
                    acc[i][j] += a[i] * b[j];
        }
        __syncthreads();
    }

    #pragma unroll
    for (int i = 0; i < TM; ++i) {
        int gm = m0 + ty*TM + i;
        if (gm >= M) continue;
        #pragma unroll
        for (int j = 0; j < TN; ++j) {
            int gn = n0 + tx*TN + j;
            if (gn >= N) continue;
            float v = acc[i][j];
            if (bias) v += bias[gn];
            if (EPI == 0) {
                C[(long)gm*ldc + gn] = v;
            } else {
                int bb = gm >> 10;          // gm = b*1024 + t
                int t  = gm & 1023;
                C[(long)(bb*NMEL + gn)*NT_SEQ + t] = v;
            }
        }
    }
}

// ---------------- elementwise: w *= sigmoid(mask) ----------------
__global__ void mask_kernel(float* __restrict__ w, const float* __restrict__ mask, int n)
{
    int i = blockIdx.x * blockDim.x + threadIdx.x;
    if (i < n) w[i] *= 1.f / (1.f + __expf(-mask[i]));
}

// ---------------- bvec[e] = sum_d b_in[d] * Q[d,e] ----------------
__global__ void bvec_kernel(const float* __restrict__ b_in, const float* __restrict__ Q,
                            float* __restrict__ bvec)
{
    int e = blockIdx.x * blockDim.x + threadIdx.x;
    if (e >= DD) return;
    float s = 0.f;
    for (int d = 0; d < DD; ++d) s += b_in[d] * Q[(long)d*DD + e];
    bvec[e] = s;
}

// ---------------- grouped conv1d (groups=16, k=3, pad=1), [b,t,c] layout ----------------
// optional exact GELU on output
template<bool DO_GELU>
__global__ __launch_bounds__(256)
void conv_kernel(const float* __restrict__ in, const float* __restrict__ w,
                 const float* __restrict__ bias, float* __restrict__ out)
{
    constexpr int TT = 8;                 // t-tile
    __shared__ float sm[TT+2][DD];        // 40 KB
    const int blk = blockIdx.x;
    const int b  = blk / (NT_SEQ / TT);
    const int t0 = (blk % (NT_SEQ / TT)) * TT;
    const float* inb = in + (long)b * NT_SEQ * DD;
    const int tid = threadIdx.x;

    for (int idx = tid; idx < (TT+2)*DD; idx += 256) {
        int r = idx / DD, c = idx % DD;
        int t = t0 - 1 + r;
        sm[r][c] = (t >= 0 && t < NT_SEQ) ? inb[(long)t*DD + c] : 0.f;
    }
    __syncthreads();

    const int cbase = tid * 4;            // 4 output channels per thread
    const int g = cbase >> 6;             // group (64 channels/group)
    float acc[4][TT];
    #pragma unroll
    for (int cc = 0; cc < 4; ++cc) {
        float bb = bias[cbase + cc];
        #pragma unroll
        for (int tt = 0; tt < TT; ++tt) acc[cc][tt] = bb;
    }
    const float* wp = w + (long)cbase * 192;   // w[c][ci][k], 64*3 per channel

    for (int ci = 0; ci < 64; ++ci) {
        float x[TT+2];
        #pragma unroll
        for (int r = 0; r < TT+2; ++r) x[r] = sm[r][g*64 + ci];
        #pragma unroll
        for (int cc = 0; cc < 4; ++cc) {
            float w0 = wp[cc*192 + ci*3 + 0];
            float w1 = wp[cc*192 + ci*3 + 1];
            float w2 = wp[cc*192 + ci*3 + 2];
            #pragma unroll
            for (int tt = 0; tt < TT; ++tt)
                acc[cc][tt] += w0*x[tt] + w1*x[tt+1] + w2*x[tt+2];
        }
    }

    float* outb = out + (long)b * NT_SEQ * DD;
    #pragma unroll
    for (int tt = 0; tt < TT; ++tt) {
        float4 o;
        float v0 = acc[0][tt], v1 = acc[1][tt], v2 = acc[2][tt], v3 = acc[3][tt];
        if (DO_GELU) {
            v0 = 0.5f*v0*(1.f + erff(v0*0.70710678118654752f));
            v1 = 0.5f*v1*(1.f + erff(v1*0.70710678118654752f));
            v2 = 0.5f*v2*(1.f + erff(v2*0.70710678118654752f));
            v3 = 0.5f*v3*(1.f + erff(v3*0.70710678118654752f));
        }
        o.x = v0; o.y = v1; o.z = v2; o.w = v3;
        *(float4*)(outb + (long)(t0+tt)*DD + cbase) = o;
    }
}

// ---------------- LayerNorm over last dim (1024) ----------------
__global__ __launch_bounds__(256)
void ln_kernel(const float* __restrict__ in, const float* __restrict__ gam,
               const float* __restrict__ bet, float* __restrict__ out)
{
    __shared__ float s1[8], s2[8];
    const int row = blockIdx.x;
    const int tid = threadIdx.x;
    const float4* x4 = (const float4*)(in + (long)row * DD);
    float4 v = x4[tid];
    float s = v.x + v.y + v.z + v.w;
    float q = v.x*v.x + v.y*v.y + v.z*v.z + v.w*v.w;
    #pragma unroll
    for (int o = 16; o > 0; o >>= 1) {
        s += __shfl_xor_sync(0xFFFFFFFFu, s, o);
        q += __shfl_xor_sync(0xFFFFFFFFu, q, o);
    }
    if ((tid & 31) == 0) { s1[tid >> 5] = s; s2[tid >> 5] = q; }
    __syncthreads();
    float ts = 0.f, tq = 0.f;
    #pragma unroll
    for (int i = 0; i < 8; ++i) { ts += s1[i]; tq += s2[i]; }
    const float mu   = ts * (1.f / DD);
    const float var  = tq * (1.f / DD) - mu * mu;
    const float rstd = rsqrtf(var + 1e-5f);
    float4 g4 = ((const float4*)gam)[tid];
    float4 b4 = ((const float4*)bet)[tid];
    v.x = (v.x - mu) * rstd * g4.x + b4.x;
    v.y = (v.y - mu) * rstd * g4.y + b4.y;
    v.z = (v.z - mu) * rstd * g4.z + b4.z;
    v.w = (v.w - mu) * rstd * g4.w + b4.w;
    ((float4*)(out + (long)row * DD))[tid] = v;
}

// ---------------- launch ----------------
extern "C" void kernel_launch(void* const* d_in, const int* in_sizes, int n_in,
                              void* d_out, int out_size)
{
    (void)in_sizes; (void)n_in; (void)out_size;
    const float* llama = (const float*)d_in[0];
    // d_in[1] = timesteps (unused by the reference)
    const float* W_in  = (const float*)d_in[2];
    const float* b_in  = (const float*)d_in[3];
    const float* P     = (const float*)d_in[4];
    const float* smask = (const float*)d_in[5];
    const float* Wd    = (const float*)d_in[6];
    const float* bd    = (const float*)d_in[7];
    const float* c1w   = (const float*)d_in[8];
    const float* c1b   = (const float*)d_in[9];
    const float* c2w   = (const float*)d_in[10];
    const float* c2b   = (const float*)d_in[11];
    const float* lng   = (const float*)d_in[12];
    const float* lnb   = (const float*)d_in[13];
    const float* Wmel  = (const float*)d_in[14];
    const float* bmel  = (const float*)d_in[15];
    float* out = (float*)d_out;

    void* p;
    cudaGetSymbolAddress(&p, g_bufA);  float* bufA  = (float*)p;
    cudaGetSymbolAddress(&p, g_bufB);  float* bufB  = (float*)p;
    cudaGetSymbolAddress(&p, g_Q);     float* Qm    = (float*)p;
    cudaGetSymbolAddress(&p, g_Wc);    float* Wc    = (float*)p;
    cudaGetSymbolAddress(&p, g_bvec);  float* bvec  = (float*)p;
    cudaGetSymbolAddress(&p, g_fused); float* fused = (float*)p;
    cudaGetSymbolAddress(&p, g_h1);    float* h1    = (float*)p;
    cudaGetSymbolAddress(&p, g_h2);    float* h2    = (float*)p;

    // 1) w_proj = W_in @ Wd^T + bd (col bias)    [1024,1024]
    gemm_kernel<128,128,16,8,8,false,true,0><<<dim3(DD/128, DD/128), 256>>>(
        W_in, Wd, bd, bufA, DD, DD, LL, LL, LL, DD);

    // 2) tmp = P^T @ w_proj
    gemm_kernel<64,64,16,4,4,true,false,0><<<dim3(DD/64, DD/64), 256>>>(
        P, bufA, nullptr, bufB, DD, DD, DD, DD, DD, DD);

    // 3) w_prime = tmp @ P
    gemm_kernel<64,64,16,4,4,false,false,0><<<dim3(DD/64, DD/64), 256>>>(
        bufB, P, nullptr, bufA, DD, DD, DD, DD, DD, DD);

    // 4) masked_w = w_prime * sigmoid(mask)
    mask_kernel<<<(DD*DD + 255)/256, 256>>>(bufA, smask, DD*DD);

    // 5) S = P @ masked_w^T
    gemm_kernel<64,64,16,4,4,false,true,0><<<dim3(DD/64, DD/64), 256>>>(
        P, bufA, nullptr, bufB, DD, DD, DD, DD, DD, DD);

    // 6) Q = S @ P^T
    gemm_kernel<64,64,16,4,4,false,true,0><<<dim3(DD/64, DD/64), 256>>>(
        bufB, P, nullptr, Qm, DD, DD, DD, DD, DD, DD);

    // 7) W_c = W_in^T @ Q   [3072,1024]
    gemm_kernel<128,128,16,8,8,true,false,0><<<dim3(DD/128, LL/128), 256>>>(
        W_in, Qm, nullptr, Wc, LL, DD, DD, LL, DD, DD);

    // 8) bvec = b_in @ Q
    bvec_kernel<<<(DD + 255)/256, 256>>>(b_in, Qm, bvec);

    // 9) fused = llama @ W_c + bvec   [4096,1024]
    gemm_kernel<128,128,16,8,8,false,false,0><<<dim3(DD/128, ROWS/128), 256>>>(
        llama, Wc, bvec, fused, ROWS, DD, LL, LL, DD, DD);

    // 10) conv1 + GELU (exact)
    conv_kernel<true><<<NB * (NT_SEQ/8), 256>>>(fused, c1w, c1b, h1);

    // 11) conv2
    conv_kernel<false><<<NB * (NT_SEQ/8), 256>>>(h1, c2w, c2b, h2);

    // 12) LayerNorm -> reuse fused as xn
    ln_kernel<<<ROWS, 256>>>(h2, lng, lnb, fused);

    // 13) mel = xn @ Wmel^T + bmel, written transposed to out[B, NMEL, T]
    gemm_kernel<64,64,16,4,4,false,true,1><<<dim3((NMEL+63)/64, ROWS/64), 256>>>(
        fused, Wmel, bmel, out, ROWS, NMEL, DD, DD, DD, 0);
}

// round 5
// speedup vs baseline: 1.8717x; 1.8717x over previous
#include <cuda_runtime.h>
#include <cuda_bf16.h>
#include <stdint.h>
#include <math.h>

#define DD 1024
#define LL 3072
#define NMEL 100
#define NB 4
#define NT_SEQ 1024
#define ROWS (NB*NT_SEQ)

// ---------------- fp32 scratch ----------------
__device__ float g_wproj[DD*DD];
__device__ float g_t1[DD*DD];
__device__ float g_wprime[DD*DD];
__device__ float g_u[DD*DD];
__device__ float g_Qf[DD*DD];
__device__ float g_WcT[DD*LL];
__device__ float g_fused[ROWS*DD];
__device__ float g_h1[ROWS*DD];
__device__ float g_h2[ROWS*DD];
__device__ float g_bvec[DD];

// ---------------- bf16 split scratch ----------------
__device__ __nv_bfloat16 g_WinD_h[DD*LL];
__device__ __nv_bfloat16 g_WinD_l[DD*LL];
__device__ __nv_bfloat16 g_WdD_h[DD*LL];
__device__ __nv_bfloat16 g_WdD_l[DD*LL];
__device__ __nv_bfloat16 g_WinT_h[LL*DD];
__device__ __nv_bfloat16 g_WinT_l[LL*DD];
__device__ __nv_bfloat16 g_Lla_h[ROWS*LL];
__device__ __nv_bfloat16 g_Lla_l[ROWS*LL];
__device__ __nv_bfloat16 g_Pd_h[DD*DD];
__device__ __nv_bfloat16 g_Pd_l[DD*DD];
__device__ __nv_bfloat16 g_Pt_h[DD*DD];
__device__ __nv_bfloat16 g_Pt_l[DD*DD];
__device__ __nv_bfloat16 g_wpT_h[DD*DD];
__device__ __nv_bfloat16 g_wpT_l[DD*DD];
__device__ __nv_bfloat16 g_t1s_h[DD*DD];
__device__ __nv_bfloat16 g_t1s_l[DD*DD];
__device__ __nv_bfloat16 g_S_h[DD*DD];
__device__ __nv_bfloat16 g_S_l[DD*DD];
__device__ __nv_bfloat16 g_uT_h[DD*DD];
__device__ __nv_bfloat16 g_uT_l[DD*DD];
__device__ __nv_bfloat16 g_QT_h[DD*DD];
__device__ __nv_bfloat16 g_QT_l[DD*DD];
__device__ __nv_bfloat16 g_WcTs_h[DD*LL];
__device__ __nv_bfloat16 g_WcTs_l[DD*LL];
__device__ __nv_bfloat16 g_xn_h[ROWS*DD];
__device__ __nv_bfloat16 g_xn_l[ROWS*DD];
__device__ __nv_bfloat16 g_Wmel_h[128*DD];
__device__ __nv_bfloat16 g_Wmel_l[128*DD];

// ---------------- device helpers ----------------
__device__ __forceinline__ void split2(float x, __nv_bfloat16& h, __nv_bfloat16& l) {
    h = __float2bfloat16_rn(x);
    l = __float2bfloat16_rn(x - __bfloat162float(h));
}

__device__ __forceinline__ unsigned smaddr(const void* p) {
    return (unsigned)__cvta_generic_to_shared(p);
}

__device__ __forceinline__ void ldm_x4(uint32_t* r, unsigned a) {
    asm volatile("ldmatrix.sync.aligned.m8n8.x4.shared.b16 {%0,%1,%2,%3}, [%4];"
        : "=r"(r[0]), "=r"(r[1]), "=r"(r[2]), "=r"(r[3]) : "r"(a));
}

__device__ __forceinline__ void mma16816(float* d, const uint32_t* a, const uint32_t* b) {
    asm volatile("mma.sync.aligned.m16n8k16.row.col.f32.bf16.bf16.f32 "
        "{%0,%1,%2,%3}, {%4,%5,%6,%7}, {%8,%9}, {%0,%1,%2,%3};"
        : "+f"(d[0]), "+f"(d[1]), "+f"(d[2]), "+f"(d[3])
        : "r"(a[0]), "r"(a[1]), "r"(a[2]), "r"(a[3]), "r"(b[0]), "r"(b[1]));
}

// ---------------- bodies ----------------
__device__ void split_dir_body(const float* in, __nv_bfloat16* hi, __nv_bfloat16* lo, int n4)
{
    int i = blockIdx.x * blockDim.x + threadIdx.x;
    if (i >= n4) return;
    float4 v = ((const float4*)in)[i];
    __nv_bfloat16 h0, h1, h2, h3, l0, l1, l2, l3;
    split2(v.x, h0, l0);
    split2(v.y, h1, l1);
    split2(v.z, h2, l2);
    split2(v.w, h3, l3);
    ((__nv_bfloat162*)hi)[2*i+0] = __nv_bfloat162(h0, h1);
    ((__nv_bfloat162*)hi)[2*i+1] = __nv_bfloat162(h2, h3);
    ((__nv_bfloat162*)lo)[2*i+0] = __nv_bfloat162(l0, l1);
    ((__nv_bfloat162*)lo)[2*i+1] = __nv_bfloat162(l2, l3);
}

template<bool SIG>
__device__ void split_trans_body(const float* in, const float* mask,
                                 __nv_bfloat16* hi, __nv_bfloat16* lo, int P_, int Q_)
{
    __shared__ float t[32][33];
    int p0 = blockIdx.x * 32;
    int q0 = blockIdx.y * 32;
    int tx = threadIdx.x;
    int ty = threadIdx.y;
    #pragma unroll
    for (int dy = 0; dy < 32; dy += 8) {
        size_t idx = (size_t)(p0 + ty + dy) * Q_ + q0 + tx;
        float v = in[idx];
        if (SIG) v *= 1.f / (1.f + __expf(-mask[idx]));
        t[ty + dy][tx] = v;
    }
    __syncthreads();
    #pragma unroll
    for (int dy = 0; dy < 32; dy += 8) {
        float v = t[tx][ty + dy];
        __nv_bfloat16 h, l;
        split2(v, h, l);
        size_t o = (size_t)(q0 + ty + dy) * P_ + p0 + tx;
        hi[o] = h;
        lo[o] = l;
    }
}

// GEMM: C[M,N] = A[M,K] @ Bt[N,K]^T (+bias), 3-term bf16 split, fp32 accum.
template<int EPI>
__device__ void gemm_body(const __nv_bfloat16* Ahi, const __nv_bfloat16* Alo,
                          const __nv_bfloat16* Bhi, const __nv_bfloat16* Blo,
                          const float* bias, float* C, int M, int N, int K)
{
    __shared__ __nv_bfloat16 sAh[128][40];
    __shared__ __nv_bfloat16 sAl[128][40];
    __shared__ __nv_bfloat16 sBh[128][40];
    __shared__ __nv_bfloat16 sBl[128][40];
    const int tid  = threadIdx.x;
    const int warp = tid >> 5;
    const int lane = tid & 31;
    const int wm = warp & 1;
    const int wn = warp >> 1;
    const int m0b = blockIdx.y * 128;
    const int n0b = blockIdx.x * 128;
    const int wm0 = wm * 64;
    const int wn0 = wn * 32;

    float acc[4][4][4];
    #pragma unroll
    for (int i = 0; i < 4; ++i)
        #pragma unroll
        for (int j = 0; j < 4; ++j)
            #pragma unroll
            for (int c = 0; c < 4; ++c) acc[i][j][c] = 0.f;

    const int lr0 = tid >> 2;
    const int lc  = (tid & 3) * 8;
    const int a_row = (lane & 15);
    const int a_col = (lane >> 4) * 8;
    const int b_row = (lane & 7) + ((lane >> 4) << 3);
    const int b_col = ((lane >> 3) & 1) * 8;

    for (int k0 = 0; k0 < K; k0 += 32) {
        #pragma unroll
        for (int h = 0; h < 2; ++h) {
            int r = lr0 + h * 64;
            size_t ga = (size_t)(m0b + r) * K + k0 + lc;
            size_t gb = (size_t)(n0b + r) * K + k0 + lc;
            *(uint4*)&sAh[r][lc] = *(const uint4*)(Ahi + ga);
            *(uint4*)&sAl[r][lc] = *(const uint4*)(Alo + ga);
            *(uint4*)&sBh[r][lc] = *(const uint4*)(Bhi + gb);
            *(uint4*)&sBl[r][lc] = *(const uint4*)(Blo + gb);
        }
        __syncthreads();

        #pragma unroll
        for (int ks = 0; ks < 32; ks += 16) {
            uint32_t ah[4][4];
            uint32_t al[4][4];
            uint32_t bh[4][2];
            uint32_t bl[4][2];
            #pragma unroll
            for (int mi = 0; mi < 4; ++mi) {
                ldm_x4(ah[mi], smaddr(&sAh[wm0 + mi*16 + a_row][ks + a_col]));
                ldm_x4(al[mi], smaddr(&sAl[wm0 + mi*16 + a_row][ks + a_col]));
            }
            #pragma unroll
            for (int njp = 0; njp < 2; ++njp) {
                uint32_t t[4];
                ldm_x4(t, smaddr(&sBh[wn0 + njp*16 + b_row][ks + b_col]));
                bh[njp*2][0] = t[0];
                bh[njp*2][1] = t[1];
                bh[njp*2+1][0] = t[2];
                bh[njp*2+1][1] = t[3];
                ldm_x4(t, smaddr(&sBl[wn0 + njp*16 + b_row][ks + b_col]));
                bl[njp*2][0] = t[0];
                bl[njp*2][1] = t[1];
                bl[njp*2+1][0] = t[2];
                bl[njp*2+1][1] = t[3];
            }
            #pragma unroll
            for (int mi = 0; mi < 4; ++mi)
                #pragma unroll
                for (int nj = 0; nj < 4; ++nj) {
                    mma16816(acc[mi][nj], ah[mi], bh[nj]);
                    mma16816(acc[mi][nj], ah[mi], bl[nj]);
                    mma16816(acc[mi][nj], al[mi], bh[nj]);
                }
        }
        __syncthreads();
    }

    const int g = lane >> 2;
    const int tg = lane & 3;
    #pragma unroll
    for (int mi = 0; mi < 4; ++mi)
        #pragma unroll
        for (int nj = 0; nj < 4; ++nj) {
            int m = m0b + wm0 + mi * 16 + g;
            int n = n0b + wn0 + nj * 8 + tg * 2;
            float v0 = acc[mi][nj][0];
            float v1 = acc[mi][nj][1];
            float v2 = acc[mi][nj][2];
            float v3 = acc[mi][nj][3];
            if (EPI == 0) {
                if (bias) {
                    v0 += bias[n];
                    v1 += bias[n+1];
                    v2 += bias[n];
                    v3 += bias[n+1];
                }
                C[(size_t)m * N + n]       = v0;
                C[(size_t)m * N + n + 1]   = v1;
                C[(size_t)(m+8) * N + n]   = v2;
                C[(size_t)(m+8) * N + n+1] = v3;
            } else {
                float bn0 = (n < NMEL) ? bias[n] : 0.f;
                float bn1 = (n + 1 < NMEL) ? bias[n + 1] : 0.f;
                v0 += bn0;
                v1 += bn1;
                v2 += bn0;
                v3 += bn1;
                int bb = m >> 10;
                int t = m & 1023;
                int bb2 = (m + 8) >> 10;
                int t2 = (m + 8) & 1023;
                if (n < NMEL) {
                    C[(size_t)(bb*NMEL + n) * NT_SEQ + t] = v0;
                    C[(size_t)(bb2*NMEL + n) * NT_SEQ + t2] = v2;
                }
                if (n + 1 < NMEL) {
                    C[(size_t)(bb*NMEL + n+1) * NT_SEQ + t] = v1;
                    C[(size_t)(bb2*NMEL + n+1) * NT_SEQ + t2] = v3;
                }
            }
        }
}

template<bool DO_GELU>
__device__ void conv_body(const float* in, const float* w, const float* bias, float* out)
{
    __shared__ float sm[10][DD];
    const int blk = blockIdx.x;
    const int b  = blk / (NT_SEQ / 8);
    const int t0 = (blk % (NT_SEQ / 8)) * 8;
    const float* inb = in + (size_t)b * NT_SEQ * DD;
    const int tid = threadIdx.x;

    for (int idx = tid; idx < 10 * DD; idx += 256) {
        int r = idx / DD;
        int c = idx % DD;
        int t = t0 - 1 + r;
        sm[r][c] = (t >= 0 && t < NT_SEQ) ? inb[(size_t)t*DD + c] : 0.f;
    }
    __syncthreads();

    const int cbase = tid * 4;
    const int g = cbase >> 6;
    float acc[4][8];
    #pragma unroll
    for (int cc = 0; cc < 4; ++cc) {
        float bb = bias[cbase + cc];
        #pragma unroll
        for (int tt = 0; tt < 8; ++tt) acc[cc][tt] = bb;
    }
    const float* wp = w + (size_t)cbase * 192;

    for (int ci = 0; ci < 64; ++ci) {
        float x[10];
        #pragma unroll
        for (int r = 0; r < 10; ++r) x[r] = sm[r][g*64 + ci];
        #pragma unroll
        for (int cc = 0; cc < 4; ++cc) {
            float w0 = wp[cc*192 + ci*3 + 0];
            float w1 = wp[cc*192 + ci*3 + 1];
            float w2 = wp[cc*192 + ci*3 + 2];
            #pragma unroll
            for (int tt = 0; tt < 8; ++tt)
                acc[cc][tt] += w0*x[tt] + w1*x[tt+1] + w2*x[tt+2];
        }
    }

    float* outb = out + (size_t)b * NT_SEQ * DD;
    #pragma unroll
    for (int tt = 0; tt < 8; ++tt) {
        float v0 = acc[0][tt];
        float v1 = acc[1][tt];
        float v2 = acc[2][tt];
        float v3 = acc[3][tt];
        if (DO_GELU) {
            v0 = 0.5f*v0*(1.f + erff(v0*0.70710678118654752f));
            v1 = 0.5f*v1*(1.f + erff(v1*0.70710678118654752f));
            v2 = 0.5f*v2*(1.f + erff(v2*0.70710678118654752f));
            v3 = 0.5f*v3*(1.f + erff(v3*0.70710678118654752f));
        }
        float4 o;
        o.x = v0;
        o.y = v1;
        o.z = v2;
        o.w = v3;
        *(float4*)(outb + (size_t)(t0+tt)*DD + cbase) = o;
    }
}

__device__ void ln_body(const float* in, const float* gam, const float* bet,
                        __nv_bfloat16* oh, __nv_bfloat16* ol)
{
    __shared__ float s1[8];
    __shared__ float s2[8];
    const int row = blockIdx.x;
    const int tid = threadIdx.x;
    const float4* x4 = (const float4*)(in + (size_t)row * DD);
    float4 v = x4[tid];
    float s = v.x + v.y + v.z + v.w;
    float q = v.x*v.x + v.y*v.y + v.z*v.z + v.w*v.w;
    #pragma unroll
    for (int o = 16; o > 0; o >>= 1) {
        s += __shfl_xor_sync(0xFFFFFFFFu, s, o);
        q += __shfl_xor_sync(0xFFFFFFFFu, q, o);
    }
    if ((tid & 31) == 0) {
        s1[tid >> 5] = s;
        s2[tid >> 5] = q;
    }
    __syncthreads();
    float ts = 0.f;
    float tq = 0.f;
    #pragma unroll
    for (int i = 0; i < 8; ++i) {
        ts += s1[i];
        tq += s2[i];
    }
    const float mu   = ts * (1.f / DD);
    const float var  = tq * (1.f / DD) - mu * mu;
    const float rstd = rsqrtf(var + 1e-5f);
    float4 g4 = ((const float4*)gam)[tid];
    float4 b4 = ((const float4*)bet)[tid];
    float y0 = (v.x - mu) * rstd * g4.x + b4.x;
    float y1 = (v.y - mu) * rstd * g4.y + b4.y;
    float y2 = (v.z - mu) * rstd * g4.z + b4.z;
    float y3 = (v.w - mu) * rstd * g4.w + b4.w;
    __nv_bfloat16 h0, h1, h2, h3, l0, l1, l2, l3;
    split2(y0, h0, l0);
    split2(y1, h1, l1);
    split2(y2, h2, l2);
    split2(y3, h3, l3);
    size_t o = (size_t)row * DD + tid * 4;
    ((__nv_bfloat162*)(oh + o))[0] = __nv_bfloat162(h0, h1);
    ((__nv_bfloat162*)(oh + o))[1] = __nv_bfloat162(h2, h3);
    ((__nv_bfloat162*)(ol + o))[0] = __nv_bfloat162(l0, l1);
    ((__nv_bfloat162*)(ol + o))[1] = __nv_bfloat162(l2, l3);
}

// ---------------- wrapper kernels (bind globals by symbol) ----------------
__global__ void k_split_Win(const float* W_in) { split_dir_body(W_in, g_WinD_h, g_WinD_l, DD*LL/4); }
__global__ void k_split_Wd(const float* Wd)    { split_dir_body(Wd, g_WdD_h, g_WdD_l, DD*LL/4); }
__global__ void k_split_llama(const float* x)  { split_dir_body(x, g_Lla_h, g_Lla_l, ROWS*LL/4); }
__global__ void k_split_Pdir(const float* P)   { split_dir_body(P, g_Pd_h, g_Pd_l, DD*DD/4); }
__global__ void k_split_t1()                   { split_dir_body(g_t1, g_t1s_h, g_t1s_l, DD*DD/4); }
__global__ void k_split_WcT()                  { split_dir_body(g_WcT, g_WcTs_h, g_WcTs_l, DD*LL/4); }

__global__ void k_trans_WinT(const float* W_in) { split_trans_body<false>(W_in, 0, g_WinT_h, g_WinT_l, DD, LL); }
__global__ void k_trans_PT(const float* P)      { split_trans_body<false>(P, 0, g_Pt_h, g_Pt_l, DD, DD); }
__global__ void k_trans_wpT()                   { split_trans_body<false>(g_wproj, 0, g_wpT_h, g_wpT_l, DD, DD); }
__global__ void k_trans_S(const float* mask)    { split_trans_body<true>(g_wprime, mask, g_S_h, g_S_l, DD, DD); }
__global__ void k_trans_uT()                    { split_trans_body<false>(g_u, 0, g_uT_h, g_uT_l, DD, DD); }
__global__ void k_trans_QT()                    { split_trans_body<false>(g_Qf, 0, g_QT_h, g_QT_l, DD, DD); }

__global__ void k_split_mel(const float* Wmel)
{
    int i = blockIdx.x * 256 + threadIdx.x;
    int r = i >> 10;
    float v = (r < NMEL) ? Wmel[(size_t)r * DD + (i & 1023)] : 0.f;
    __nv_bfloat16 h, l;
    split2(v, h, l);
    g_Wmel_h[i] = h;
    g_Wmel_l[i] = l;
}

__global__ __launch_bounds__(256) void k_gemm_wproj(const float* bd)
{ gemm_body<0>(g_WinD_h, g_WinD_l, g_WdD_h, g_WdD_l, bd, g_wproj, DD, DD, LL); }

__global__ __launch_bounds__(256) void k_gemm_t1()
{ gemm_body<0>(g_Pt_h, g_Pt_l, g_wpT_h, g_wpT_l, 0, g_t1, DD, DD, DD); }

__global__ __launch_bounds__(256) void k_gemm_wprime()
{ gemm_body<0>(g_t1s_h, g_t1s_l, g_Pt_h, g_Pt_l, 0, g_wprime, DD, DD, DD); }

__global__ __launch_bounds__(256) void k_gemm_u()
{ gemm_body<0>(g_S_h, g_S_l, g_Pd_h, g_Pd_l, 0, g_u, DD, DD, DD); }

__global__ __launch_bounds__(256) void k_gemm_Q()
{ gemm_body<0>(g_Pd_h, g_Pd_l, g_uT_h, g_uT_l, 0, g_Qf, DD, DD, DD); }

__global__ __launch_bounds__(256) void k_gemm_WcT()
{ gemm_body<0>(g_QT_h, g_QT_l, g_WinT_h, g_WinT_l, 0, g_WcT, DD, LL, DD); }

__global__ __launch_bounds__(256) void k_gemm_fused()
{ gemm_body<0>(g_Lla_h, g_Lla_l, g_WcTs_h, g_WcTs_l, g_bvec, g_fused, ROWS, DD, LL); }

__global__ __launch_bounds__(256) void k_gemm_mel(const float* bmel, float* out)
{ gemm_body<1>(g_xn_h, g_xn_l, g_Wmel_h, g_Wmel_l, bmel, out, ROWS, 128, DD); }

__global__ void k_bvec(const float* b_in)
{
    int e = blockIdx.x * blockDim.x + threadIdx.x;
    if (e >= DD) return;
    float s = 0.f;
    for (int d = 0; d < DD; ++d) s += b_in[d] * g_Qf[(size_t)d * DD + e];
    g_bvec[e] = s;
}

__global__ __launch_bounds__(256) void k_conv1(const float* w, const float* b)
{ conv_body<true>(g_fused, w, b, g_h1); }

__global__ __launch_bounds__(256) void k_conv2(const float* w, const float* b)
{ conv_body<false>(g_h1, w, b, g_h2); }

__global__ __launch_bounds__(256) void k_ln(const float* g, const float* b)
{ ln_body(g_h2, g, b, g_xn_h, g_xn_l); }

// ---------------- launch ----------------
extern "C" void kernel_launch(void* const* d_in, const int* in_sizes, int n_in,
                              void* d_out, int out_size)
{
    (void)in_sizes;
    (void)n_in;
    (void)out_size;
    const float* llama = (const float*)d_in[0];
    const float* W_in  = (const float*)d_in[2];
    const float* b_in  = (const float*)d_in[3];
    const float* P     = (const float*)d_in[4];
    const float* smask = (const float*)d_in[5];
    const float* bd    = (const float*)d_in[7];
    const float* c1w   = (const float*)d_in[8];
    const float* c1b   = (const float*)d_in[9];
    const float* c2w   = (const float*)d_in[10];
    const float* c2b   = (const float*)d_in[11];
    const float* lng   = (const float*)d_in[12];
    const float* lnb   = (const float*)d_in[13];
    const float* Wmel  = (const float*)d_in[14];
    const float* bmel  = (const float*)d_in[15];
    const float* Wd    = (const float*)d_in[6];
    float* out = (float*)d_out;

    dim3 tb(32, 8);

    k_split_Win<<<DD*LL/4/256, 256>>>(W_in);
    k_split_Wd<<<DD*LL/4/256, 256>>>(Wd);
    k_trans_WinT<<<dim3(DD/32, LL/32), tb>>>(W_in);
    k_split_llama<<<ROWS*LL/4/256, 256>>>(llama);
    k_split_Pdir<<<DD*DD/4/256, 256>>>(P);
    k_trans_PT<<<dim3(DD/32, DD/32), tb>>>(P);
    k_split_mel<<<128*DD/256, 256>>>(Wmel);

    k_gemm_wproj<<<dim3(DD/128, DD/128), 256>>>(bd);
    k_trans_wpT<<<dim3(DD/32, DD/32), tb>>>();
    k_gemm_t1<<<dim3(DD/128, DD/128), 256>>>();
    k_split_t1<<<DD*DD/4/256, 256>>>();
    k_gemm_wprime<<<dim3(DD/128, DD/128), 256>>>();
    k_trans_S<<<dim3(DD/32, DD/32), tb>>>(smask);
    k_gemm_u<<<dim3(DD/128, DD/128), 256>>>();
    k_trans_uT<<<dim3(DD/32, DD/32), tb>>>();
    k_gemm_Q<<<dim3(DD/128, DD/128), 256>>>();
    k_trans_QT<<<dim3(DD/32, DD/32), tb>>>();
    k_bvec<<<DD/256, 256>>>(b_in);
    k_gemm_WcT<<<dim3(LL/128, DD/128), 256>>>();
    k_split_WcT<<<DD*LL/4/256, 256>>>();
    k_gemm_fused<<<dim3(DD/128, ROWS/128), 256>>>();

    k_conv1<<<NB * (NT_SEQ/8), 256>>>(c1w, c1b);
    k_conv2<<<NB * (NT_SEQ/8), 256>>>(c2w, c2b);
    k_ln<<<ROWS, 256>>>(lng, lnb);
    k_gemm_mel<<<dim3(1, ROWS/128), 256>>>(bmel, out);
}

// round 7
// speedup vs baseline: 2.2025x; 1.1768x over previous
#include <cuda_runtime.h>
#include <cuda_bf16.h>
#include <stdint.h>
#include <math.h>

#define DD 1024
#define LL 3072
#define NMEL 100
#define NB 4
#define NT_SEQ 1024
#define ROWS (NB*NT_SEQ)

// ---------------- fp32 scratch ----------------
__device__ float g_wproj[DD*DD];
__device__ float g_t1[DD*DD];
__device__ float g_wprime[DD*DD];
__device__ float g_u[DD*DD];
__device__ float g_Qf[DD*DD];
__device__ float g_WcT[DD*LL];
__device__ float g_fused[ROWS*DD];
__device__ float g_h1[ROWS*DD];
__device__ float g_h2[ROWS*DD];
__device__ float g_bvec[DD];

// ---------------- bf16 split scratch ----------------
__device__ __nv_bfloat16 g_WinD_h[DD*LL];
__device__ __nv_bfloat16 g_WinD_l[DD*LL];
__device__ __nv_bfloat16 g_WdD_h[DD*LL];
__device__ __nv_bfloat16 g_WdD_l[DD*LL];
__device__ __nv_bfloat16 g_WinT_h[LL*DD];
__device__ __nv_bfloat16 g_WinT_l[LL*DD];
__device__ __nv_bfloat16 g_Lla_h[ROWS*LL];
__device__ __nv_bfloat16 g_Lla_l[ROWS*LL];
__device__ __nv_bfloat16 g_Pd_h[DD*DD];
__device__ __nv_bfloat16 g_Pd_l[DD*DD];
__device__ __nv_bfloat16 g_Pt_h[DD*DD];
__device__ __nv_bfloat16 g_Pt_l[DD*DD];
__device__ __nv_bfloat16 g_wpT_h[DD*DD];
__device__ __nv_bfloat16 g_wpT_l[DD*DD];
__device__ __nv_bfloat16 g_t1s_h[DD*DD];
__device__ __nv_bfloat16 g_t1s_l[DD*DD];
__device__ __nv_bfloat16 g_S_h[DD*DD];
__device__ __nv_bfloat16 g_S_l[DD*DD];
__device__ __nv_bfloat16 g_uT_h[DD*DD];
__device__ __nv_bfloat16 g_uT_l[DD*DD];
__device__ __nv_bfloat16 g_QT_h[DD*DD];
__device__ __nv_bfloat16 g_QT_l[DD*DD];
__device__ __nv_bfloat16 g_WcTs_h[DD*LL];
__device__ __nv_bfloat16 g_WcTs_l[DD*LL];
__device__ __nv_bfloat16 g_xn_h[ROWS*DD];
__device__ __nv_bfloat16 g_xn_l[ROWS*DD];
__device__ __nv_bfloat16 g_Wmel_h[128*DD];
__device__ __nv_bfloat16 g_Wmel_l[128*DD];

// ---------------- device helpers ----------------
__device__ __forceinline__ void split2(float x, __nv_bfloat16& h, __nv_bfloat16& l) {
    h = __float2bfloat16_rn(x);
    l = __float2bfloat16_rn(x - __bfloat162float(h));
}

__device__ __forceinline__ unsigned smaddr(const void* p) {
    return (unsigned)__cvta_generic_to_shared(p);
}

__device__ __forceinline__ void ldm_x4(uint32_t* r, unsigned a) {
    asm volatile("ldmatrix.sync.aligned.m8n8.x4.shared.b16 {%0,%1,%2,%3}, [%4];"
        : "=r"(r[0]), "=r"(r[1]), "=r"(r[2]), "=r"(r[3]) : "r"(a));
}

__device__ __forceinline__ void mma16816(float* d, const uint32_t* a, const uint32_t* b) {
    asm volatile("mma.sync.aligned.m16n8k16.row.col.f32.bf16.bf16.f32 "
        "{%0,%1,%2,%3}, {%4,%5,%6,%7}, {%8,%9}, {%0,%1,%2,%3};"
        : "+f"(d[0]), "+f"(d[1]), "+f"(d[2]), "+f"(d[3])
        : "r"(a[0]), "r"(a[1]), "r"(a[2]), "r"(a[3]), "r"(b[0]), "r"(b[1]));
}

__device__ __forceinline__ void cpa16(unsigned sm, const void* g) {
    asm volatile("cp.async.cg.shared.global [%0], [%1], 16;" :: "r"(sm), "l"(g));
}

__device__ __forceinline__ void cpa_commit() {
    asm volatile("cp.async.commit_group;");
}

template<int W>
__device__ __forceinline__ void cpa_wait() {
    asm volatile("cp.async.wait_group %0;" :: "n"(W));
}

// ---------------- bodies ----------------
__device__ void split_dir_body(const float* in, __nv_bfloat16* hi, __nv_bfloat16* lo, int n4)
{
    int i = blockIdx.x * blockDim.x + threadIdx.x;
    if (i >= n4) return;
    float4 v = ((const float4*)in)[i];
    __nv_bfloat16 h0, h1, h2, h3, l0, l1, l2, l3;
    split2(v.x, h0, l0);
    split2(v.y, h1, l1);
    split2(v.z, h2, l2);
    split2(v.w, h3, l3);
    ((__nv_bfloat162*)hi)[2*i+0] = __nv_bfloat162(h0, h1);
    ((__nv_bfloat162*)hi)[2*i+1] = __nv_bfloat162(h2, h3);
    ((__nv_bfloat162*)lo)[2*i+0] = __nv_bfloat162(l0, l1);
    ((__nv_bfloat162*)lo)[2*i+1] = __nv_bfloat162(l2, l3);
}

template<bool SIG>
__device__ void split_trans_body(const float* in, const float* mask,
                                 __nv_bfloat16* hi, __nv_bfloat16* lo, int P_, int Q_)
{
    __shared__ float t[32][33];
    int p0 = blockIdx.x * 32;
    int q0 = blockIdx.y * 32;
    int tx = threadIdx.x;
    int ty = threadIdx.y;
    #pragma unroll
    for (int dy = 0; dy < 32; dy += 8) {
        size_t idx = (size_t)(p0 + ty + dy) * Q_ + q0 + tx;
        float v = in[idx];
        if (SIG) v *= 1.f / (1.f + __expf(-mask[idx]));
        t[ty + dy][tx] = v;
    }
    __syncthreads();
    #pragma unroll
    for (int dy = 0; dy < 32; dy += 8) {
        float v = t[tx][ty + dy];
        __nv_bfloat16 h, l;
        split2(v, h, l);
        size_t o = (size_t)(q0 + ty + dy) * P_ + p0 + tx;
        hi[o] = h;
        lo[o] = l;
    }
}

// Pipelined split-bf16 GEMM in dynamic smem: C[M,N] = A[M,K] @ Bt[N,K]^T (+bias)
// BM = 2*MI*16, BN = 4*NJ*8, BK=32, 2-stage cp.async, 80B smem row stride.
template<int MI, int NJ, int EPI>
__device__ void gemm_body(const __nv_bfloat16* Ahi, const __nv_bfloat16* Alo,
                          const __nv_bfloat16* Bhi, const __nv_bfloat16* Blo,
                          const float* bias, float* C, int M, int N, int K)
{
    constexpr int BM = 2 * MI * 16;
    constexpr int BN = 4 * NJ * 8;
    extern __shared__ __nv_bfloat16 dyn[];
    __nv_bfloat16* sAh = dyn;
    __nv_bfloat16* sAl = sAh + 2 * BM * 40;
    __nv_bfloat16* sBh = sAl + 2 * BM * 40;
    __nv_bfloat16* sBl = sBh + 2 * BN * 40;

    const int tid = threadIdx.x;
    const int warp = tid >> 5;
    const int lane = tid & 31;
    const int wm = warp & 1;
    const int wn = warp >> 1;
    const int m0b = blockIdx.y * BM;
    const int n0b = blockIdx.x * BN;
    const int wm0 = wm * MI * 16;
    const int wn0 = wn * NJ * 8;

    float acc[MI][NJ][4];
    #pragma unroll
    for (int i = 0; i < MI; ++i)
        #pragma unroll
        for (int j = 0; j < NJ; ++j)
            #pragma unroll
            for (int c = 0; c < 4; ++c) acc[i][j][c] = 0.f;

    const int lr0 = tid >> 2;
    const int lc  = (tid & 3) * 8;
    const int a_row = lane & 15;
    const int a_col = (lane >> 4) * 8;
    const int b_row = (lane & 7) + ((lane >> 4) << 3);
    const int b_col = ((lane >> 3) & 1) * 8;

    const int nk = K >> 5;

    auto load_stage = [&](int st, int k0) {
        #pragma unroll
        for (int h = 0; h < BM / 64; ++h) {
            int r = lr0 + h * 64;
            size_t ga = (size_t)(m0b + r) * K + k0 + lc;
            cpa16(smaddr(sAh + (st * BM + r) * 40 + lc), Ahi + ga);
            cpa16(smaddr(sAl + (st * BM + r) * 40 + lc), Alo + ga);
        }
        #pragma unroll
        for (int h = 0; h < BN / 64; ++h) {
            int r = lr0 + h * 64;
            size_t gb = (size_t)(n0b + r) * K + k0 + lc;
            cpa16(smaddr(sBh + (st * BN + r) * 40 + lc), Bhi + gb);
            cpa16(smaddr(sBl + (st * BN + r) * 40 + lc), Blo + gb);
        }
    };

    auto compute_stage = [&](int st) {
        #pragma unroll
        for (int ks = 0; ks < 32; ks += 16) {
            uint32_t ah[MI][4];
            uint32_t al[MI][4];
            uint32_t bh[NJ][2];
            uint32_t bl[NJ][2];
            #pragma unroll
            for (int mi = 0; mi < MI; ++mi) {
                ldm_x4(ah[mi], smaddr(sAh + (st * BM + wm0 + mi*16 + a_row) * 40 + ks + a_col));
                ldm_x4(al[mi], smaddr(sAl + (st * BM + wm0 + mi*16 + a_row) * 40 + ks + a_col));
            }
            #pragma unroll
            for (int njp = 0; njp < NJ / 2; ++njp) {
                uint32_t t[4];
                ldm_x4(t, smaddr(sBh + (st * BN + wn0 + njp*16 + b_row) * 40 + ks + b_col));
                bh[njp*2][0] = t[0];
                bh[njp*2][1] = t[1];
                bh[njp*2+1][0] = t[2];
                bh[njp*2+1][1] = t[3];
                ldm_x4(t, smaddr(sBl + (st * BN + wn0 + njp*16 + b_row) * 40 + ks + b_col));
                bl[njp*2][0] = t[0];
                bl[njp*2][1] = t[1];
                bl[njp*2+1][0] = t[2];
                bl[njp*2+1][1] = t[3];
            }
            #pragma unroll
            for (int mi = 0; mi < MI; ++mi)
                #pragma unroll
                for (int nj = 0; nj < NJ; ++nj) {
                    mma16816(acc[mi][nj], ah[mi], bh[nj]);
                    mma16816(acc[mi][nj], ah[mi], bl[nj]);
                    mma16816(acc[mi][nj], al[mi], bh[nj]);
                }
        }
    };

    load_stage(0, 0);
    cpa_commit();
    for (int ks = 0; ks < nk; ++ks) {
        if (ks + 1 < nk) {
            load_stage((ks + 1) & 1, (ks + 1) * 32);
            cpa_commit();
            cpa_wait<1>();
        } else {
            cpa_wait<0>();
        }
        __syncthreads();
        compute_stage(ks & 1);
        __syncthreads();
    }

    const int g = lane >> 2;
    const int tg = lane & 3;
    #pragma unroll
    for (int mi = 0; mi < MI; ++mi)
        #pragma unroll
        for (int nj = 0; nj < NJ; ++nj) {
            int m = m0b + wm0 + mi * 16 + g;
            int n = n0b + wn0 + nj * 8 + tg * 2;
            float v0 = acc[mi][nj][0];
            float v1 = acc[mi][nj][1];
            float v2 = acc[mi][nj][2];
            float v3 = acc[mi][nj][3];
            if (EPI == 0) {
                if (bias) {
                    v0 += bias[n];
                    v1 += bias[n+1];
                    v2 += bias[n];
                    v3 += bias[n+1];
                }
                C[(size_t)m * N + n]       = v0;
                C[(size_t)m * N + n + 1]   = v1;
                C[(size_t)(m+8) * N + n]   = v2;
                C[(size_t)(m+8) * N + n+1] = v3;
            } else {
                float bn0 = (n < NMEL) ? bias[n] : 0.f;
                float bn1 = (n + 1 < NMEL) ? bias[n + 1] : 0.f;
                v0 += bn0;
                v1 += bn1;
                v2 += bn0;
                v3 += bn1;
                int bb = m >> 10;
                int t = m & 1023;
                int bb2 = (m + 8) >> 10;
                int t2 = (m + 8) & 1023;
                if (n < NMEL) {
                    C[(size_t)(bb*NMEL + n) * NT_SEQ + t] = v0;
                    C[(size_t)(bb2*NMEL + n) * NT_SEQ + t2] = v2;
                }
                if (n + 1 < NMEL) {
                    C[(size_t)(bb*NMEL + n+1) * NT_SEQ + t] = v1;
                    C[(size_t)(bb2*NMEL + n+1) * NT_SEQ + t2] = v3;
                }
            }
        }
}

template<bool DO_GELU>
__device__ void conv_body(const float* in, const float* w, const float* bias, float* out)
{
    __shared__ float sm[10][DD];
    const int blk = blockIdx.x;
    const int b  = blk / (NT_SEQ / 8);
    const int t0 = (blk % (NT_SEQ / 8)) * 8;
    const float* inb = in + (size_t)b * NT_SEQ * DD;
    const int tid = threadIdx.x;

    for (int idx = tid; idx < 10 * DD; idx += 256) {
        int r = idx / DD;
        int c = idx % DD;
        int t = t0 - 1 + r;
        sm[r][c] = (t >= 0 && t < NT_SEQ) ? inb[(size_t)t*DD + c] : 0.f;
    }
    __syncthreads();

    const int cbase = tid * 4;
    const int g = cbase >> 6;
    float acc[4][8];
    #pragma unroll
    for (int cc = 0; cc < 4; ++cc) {
        float bb = bias[cbase + cc];
        #pragma unroll
        for (int tt = 0; tt < 8; ++tt) acc[cc][tt] = bb;
    }
    const float* wp = w + (size_t)cbase * 192;

    for (int ci = 0; ci < 64; ++ci) {
        float x[10];
        #pragma unroll
        for (int r = 0; r < 10; ++r) x[r] = sm[r][g*64 + ci];
        #pragma unroll
        for (int cc = 0; cc < 4; ++cc) {
            float w0 = wp[cc*192 + ci*3 + 0];
            float w1 = wp[cc*192 + ci*3 + 1];
            float w2 = wp[cc*192 + ci*3 + 2];
            #pragma unroll
            for (int tt = 0; tt < 8; ++tt)
                acc[cc][tt] += w0*x[tt] + w1*x[tt+1] + w2*x[tt+2];
        }
    }

    float* outb = out + (size_t)b * NT_SEQ * DD;
    #pragma unroll
    for (int tt = 0; tt < 8; ++tt) {
        float v0 = acc[0][tt];
        float v1 = acc[1][tt];
        float v2 = acc[2][tt];
        float v3 = acc[3][tt];
        if (DO_GELU) {
            v0 = 0.5f*v0*(1.f + erff(v0*0.70710678118654752f));
            v1 = 0.5f*v1*(1.f + erff(v1*0.70710678118654752f));
            v2 = 0.5f*v2*(1.f + erff(v2*0.70710678118654752f));
            v3 = 0.5f*v3*(1.f + erff(v3*0.70710678118654752f));
        }
        float4 o;
        o.x = v0;
        o.y = v1;
        o.z = v2;
        o.w = v3;
        *(float4*)(outb + (size_t)(t0+tt)*DD + cbase) = o;
    }
}

__device__ void ln_body(const float* in, const float* gam, const float* bet,
                        __nv_bfloat16* oh, __nv_bfloat16* ol)
{
    __shared__ float s1[8];
    __shared__ float s2[8];
    const int row = blockIdx.x;
    const int tid = threadIdx.x;
    const float4* x4 = (const float4*)(in + (size_t)row * DD);
    float4 v = x4[tid];
    float s = v.x + v.y + v.z + v.w;
    float q = v.x*v.x + v.y*v.y + v.z*v.z + v.w*v.w;
    #pragma unroll
    for (int o = 16; o > 0; o >>= 1) {
        s += __shfl_xor_sync(0xFFFFFFFFu, s, o);
        q += __shfl_xor_sync(0xFFFFFFFFu, q, o);
    }
    if ((tid & 31) == 0) {
        s1[tid >> 5] = s;
        s2[tid >> 5] = q;
    }
    __syncthreads();
    float ts = 0.f;
    float tq = 0.f;
    #pragma unroll
    for (int i = 0; i < 8; ++i) {
        ts += s1[i];
        tq += s2[i];
    }
    const float mu   = ts * (1.f / DD);
    const float var  = tq * (1.f / DD) - mu * mu;
    const float rstd = rsqrtf(var + 1e-5f);
    float4 g4 = ((const float4*)gam)[tid];
    float4 b4 = ((const float4*)bet)[tid];
    float y0 = (v.x - mu) * rstd * g4.x + b4.x;
    float y1 = (v.y - mu) * rstd * g4.y + b4.y;
    float y2 = (v.z - mu) * rstd * g4.z + b4.z;
    float y3 = (v.w - mu) * rstd * g4.w + b4.w;
    __nv_bfloat16 h0, h1, h2, h3, l0, l1, l2, l3;
    split2(y0, h0, l0);
    split2(y1, h1, l1);
    split2(y2, h2, l2);
    split2(y3, h3, l3);
    size_t o = (size_t)row * DD + tid * 4;
    ((__nv_bfloat162*)(oh + o))[0] = __nv_bfloat162(h0, h1);
    ((__nv_bfloat162*)(oh + o))[1] = __nv_bfloat162(h2, h3);
    ((__nv_bfloat162*)(ol + o))[0] = __nv_bfloat162(l0, l1);
    ((__nv_bfloat162*)(ol + o))[1] = __nv_bfloat162(l2, l3);
}

// ---------------- wrapper kernels ----------------
__global__ void k_split_Win(const float* W_in) { split_dir_body(W_in, g_WinD_h, g_WinD_l, DD*LL/4); }
__global__ void k_split_Wd(const float* Wd)    { split_dir_body(Wd, g_WdD_h, g_WdD_l, DD*LL/4); }
__global__ void k_split_llama(const float* x)  { split_dir_body(x, g_Lla_h, g_Lla_l, ROWS*LL/4); }
__global__ void k_split_Pdir(const float* P)   { split_dir_body(P, g_Pd_h, g_Pd_l, DD*DD/4); }
__global__ void k_split_t1()                   { split_dir_body(g_t1, g_t1s_h, g_t1s_l, DD*DD/4); }
__global__ void k_split_WcT()                  { split_dir_body(g_WcT, g_WcTs_h, g_WcTs_l, DD*LL/4); }

__global__ void k_trans_WinT(const float* W_in) { split_trans_body<false>(W_in, 0, g_WinT_h, g_WinT_l, DD, LL); }
__global__ void k_trans_PT(const float* P)      { split_trans_body<false>(P, 0, g_Pt_h, g_Pt_l, DD, DD); }
__global__ void k_trans_wpT()                   { split_trans_body<false>(g_wproj, 0, g_wpT_h, g_wpT_l, DD, DD); }
__global__ void k_trans_S(const float* mask)    { split_trans_body<true>(g_wprime, mask, g_S_h, g_S_l, DD, DD); }
__global__ void k_trans_uT()                    { split_trans_body<false>(g_u, 0, g_uT_h, g_uT_l, DD, DD); }
__global__ void k_trans_QT()                    { split_trans_body<false>(g_Qf, 0, g_QT_h, g_QT_l, DD, DD); }

__global__ void k_split_mel(const float* Wmel)
{
    int i = blockIdx.x * 256 + threadIdx.x;
    int r = i >> 10;
    float v = (r < NMEL) ? Wmel[(size_t)r * DD + (i & 1023)] : 0.f;
    __nv_bfloat16 h, l;
    split2(v, h, l);
    g_Wmel_h[i] = h;
    g_Wmel_l[i] = l;
}

__global__ __launch_bounds__(256) void k_gemm_wproj(const float* bd)
{ gemm_body<2,4,0>(g_WinD_h, g_WinD_l, g_WdD_h, g_WdD_l, bd, g_wproj, DD, DD, LL); }

__global__ __launch_bounds__(256) void k_gemm_t1()
{ gemm_body<2,4,0>(g_Pt_h, g_Pt_l, g_wpT_h, g_wpT_l, 0, g_t1, DD, DD, DD); }

__global__ __launch_bounds__(256) void k_gemm_wprime()
{ gemm_body<2,4,0>(g_t1s_h, g_t1s_l, g_Pt_h, g_Pt_l, 0, g_wprime, DD, DD, DD); }

__global__ __launch_bounds__(256) void k_gemm_u()
{ gemm_body<2,4,0>(g_S_h, g_S_l, g_Pd_h, g_Pd_l, 0, g_u, DD, DD, DD); }

__global__ __launch_bounds__(256) void k_gemm_Q()
{ gemm_body<2,4,0>(g_Pd_h, g_Pd_l, g_uT_h, g_uT_l, 0, g_Qf, DD, DD, DD); }

__global__ __launch_bounds__(256) void k_gemm_WcT()
{ gemm_body<4,4,0>(g_QT_h, g_QT_l, g_WinT_h, g_WinT_l, 0, g_WcT, DD, LL, DD); }

__global__ __launch_bounds__(256) void k_gemm_fused()
{ gemm_body<4,4,0>(g_Lla_h, g_Lla_l, g_WcTs_h, g_WcTs_l, g_bvec, g_fused, ROWS, DD, LL); }

__global__ __launch_bounds__(256) void k_gemm_mel(const float* bmel, float* out)
{ gemm_body<2,2,1>(g_xn_h, g_xn_l, g_Wmel_h, g_Wmel_l, bmel, out, ROWS, 128, DD); }

__global__ void k_bvec(const float* b_in)
{
    int e = blockIdx.x * blockDim.x + threadIdx.x;
    if (e >= DD) return;
    float s = 0.f;
    for (int d = 0; d < DD; ++d) s += b_in[d] * g_Qf[(size_t)d * DD + e];
    g_bvec[e] = s;
}

__global__ __launch_bounds__(256) void k_conv1(const float* w, const float* b)
{ conv_body<true>(g_fused, w, b, g_h1); }

__global__ __launch_bounds__(256) void k_conv2(const float* w, const float* b)
{ conv_body<false>(g_h1, w, b, g_h2); }

__global__ __launch_bounds__(256) void k_ln(const float* g, const float* b)
{ ln_body(g_h2, g, b, g_xn_h, g_xn_l); }

// ---------------- launch ----------------
extern "C" void kernel_launch(void* const* d_in, const int* in_sizes, int n_in,
                              void* d_out, int out_size)
{
    (void)in_sizes;
    (void)n_in;
    (void)out_size;
    const float* llama = (const float*)d_in[0];
    const float* W_in  = (const float*)d_in[2];
    const float* b_in  = (const float*)d_in[3];
    const float* P     = (const float*)d_in[4];
    const float* smask = (const float*)d_in[5];
    const float* Wd    = (const float*)d_in[6];
    const float* bd    = (const float*)d_in[7];
    const float* c1w   = (const float*)d_in[8];
    const float* c1b   = (const float*)d_in[9];
    const float* c2w   = (const float*)d_in[10];
    const float* c2b   = (const float*)d_in[11];
    const float* lng   = (const float*)d_in[12];
    const float* lnb   = (const float*)d_in[13];
    const float* Wmel  = (const float*)d_in[14];
    const float* bmel  = (const float*)d_in[15];
    float* out = (float*)d_out;

    // dynamic smem budgets: 2 stages * (BM + BN) rows * 40 bf16 * 2B * (hi+lo)
    const int smem_64_128  = 2 * (64 + 128) * 40 * 2 * 2;   // 61440
    const int smem_128_128 = 2 * (128 + 128) * 40 * 2 * 2;  // 81920
    const int smem_64_64   = 2 * (64 + 64) * 40 * 2 * 2;    // 40960

    cudaFuncSetAttribute(k_gemm_wproj,  cudaFuncAttributeMaxDynamicSharedMemorySize, smem_64_128);
    cudaFuncSetAttribute(k_gemm_t1,     cudaFuncAttributeMaxDynamicSharedMemorySize, smem_64_128);
    cudaFuncSetAttribute(k_gemm_wprime, cudaFuncAttributeMaxDynamicSharedMemorySize, smem_64_128);
    cudaFuncSetAttribute(k_gemm_u,      cudaFuncAttributeMaxDynamicSharedMemorySize, smem_64_128);
    cudaFuncSetAttribute(k_gemm_Q,      cudaFuncAttributeMaxDynamicSharedMemorySize, smem_64_128);
    cudaFuncSetAttribute(k_gemm_WcT,    cudaFuncAttributeMaxDynamicSharedMemorySize, smem_128_128);
    cudaFuncSetAttribute(k_gemm_fused,  cudaFuncAttributeMaxDynamicSharedMemorySize, smem_128_128);
    cudaFuncSetAttribute(k_gemm_mel,    cudaFuncAttributeMaxDynamicSharedMemorySize, smem_64_64);

    dim3 tb(32, 8);

    k_split_Win<<<DD*LL/4/256, 256>>>(W_in);
    k_split_Wd<<<DD*LL/4/256, 256>>>(Wd);
    k_trans_WinT<<<dim3(DD/32, LL/32), tb>>>(W_in);
    k_split_llama<<<ROWS*LL/4/256, 256>>>(llama);
    k_split_Pdir<<<DD*DD/4/256, 256>>>(P);
    k_trans_PT<<<dim3(DD/32, DD/32), tb>>>(P);
    k_split_mel<<<128*DD/256, 256>>>(Wmel);

    k_gemm_wproj<<<dim3(DD/128, DD/64), 256, smem_64_128>>>(bd);
    k_trans_wpT<<<dim3(DD/32, DD/32), tb>>>();
    k_gemm_t1<<<dim3(DD/128, DD/64), 256, smem_64_128>>>();
    k_split_t1<<<DD*DD/4/256, 256>>>();
    k_gemm_wprime<<<dim3(DD/128, DD/64), 256, smem_64_128>>>();
    k_trans_S<<<dim3(DD/32, DD/32), tb>>>(smask);
    k_gemm_u<<<dim3(DD/128, DD/64), 256, smem_64_128>>>();
    k_trans_uT<<<dim3(DD/32, DD/32), tb>>>();
    k_gemm_Q<<<dim3(DD/128, DD/64), 256, smem_64_128>>>();
    k_trans_QT<<<dim3(DD/32, DD/32), tb>>>();
    k_bvec<<<DD/256, 256>>>(b_in);
    k_gemm_WcT<<<dim3(LL/128, DD/128), 256, smem_128_128>>>();
    k_split_WcT<<<DD*LL/4/256, 256>>>();
    k_gemm_fused<<<dim3(DD/128, ROWS/128), 256, smem_128_128>>>();

    k_conv1<<<NB * (NT_SEQ/8), 256>>>(c1w, c1b);
    k_conv2<<<NB * (NT_SEQ/8), 256>>>(c2w, c2b);
    k_ln<<<ROWS, 256>>>(lng, lnb);
    k_gemm_mel<<<dim3(2, ROWS/64), 256, smem_64_64>>>(bmel, out);
}